// round 16
// baseline (speedup 1.0000x reference)
#include <cuda_runtime.h>
#include <math.h>

#define NB 30
#define HWORDS (16 * 15 * NB)   // 7200 words
#define GRID_MAIN 444   // 3 blocks/SM on 148 SMs; launch_bounds(256,3) guarantees co-residency
#define FIN_BLOCKS 80   // 64 hist-MI + 16 mi_us

// ---------------- device scratch (zero-init; kernel restores zeros for graph replay) ----------------
__device__ unsigned int g_hist[32][NB * NB];
__device__ unsigned int g_maxkey[33];   // max of fenc(v)   -> mx = fdec(key)
__device__ unsigned int g_minkey[33];   // max of ~fenc(v)  -> mn = fdec(~key)
__device__ double g_l1sum;
__device__ double g_mi_hist;
__device__ double g_mi_us;
__device__ unsigned int g_arrive1;
__device__ unsigned int g_arrive2;
__device__ unsigned int g_done;
__device__ unsigned int g_hdone[32];

static __device__ __forceinline__ unsigned fenc(float f) {
    unsigned u = __float_as_uint(f);
    return (u & 0x80000000u) ? ~u : (u | 0x80000000u);
}
static __device__ __forceinline__ float fdec(unsigned u) {
    return __uint_as_float((u & 0x80000000u) ? (u ^ 0x80000000u) : ~u);
}
static __device__ __forceinline__ float edge_at(float mn, float delta, int j) {
    return __fadd_rn(mn, __fmul_rn((float)j, delta));
}

// mi_us labelize (exact linspace binning: only 16 samples -> boundary errors matter)
static __device__ void labelize16(const float* v, int* lab) {
    float mn = v[0], mx = v[0];
#pragma unroll
    for (int d = 1; d < 16; d++) { mn = fminf(mn, v[d]); mx = fmaxf(mx, v[d]); }
    float d29 = __fdiv_rn(__fsub_rn(mx, mn), 29.0f);
    float iv = 1.0f / d29;
#pragma unroll
    for (int d = 0; d < 16; d++) {
        float x = v[d];
        int j = (int)((x - mn) * iv);
        j = j < 0 ? 0 : (j > 29 ? 29 : j);
        while (j < 29 && edge_at(mn, d29, j + 1) <= x) j++;
        while (j > 0 && edge_at(mn, d29, j) > x) j--;
        lab[d] = j + 1;
    }
}

// ---------------- single fused kernel ----------------
__global__ void __launch_bounds__(256, 3) k_main(const float* __restrict__ u,
                                                 const float* __restrict__ s,
                                                 const float* __restrict__ yt,
                                                 const float* __restrict__ yp,
                                                 int n, float n_total,
                                                 float* __restrict__ out) {
    __shared__ unsigned sh[HWORDS];  // 28.8 KB: phase-2 histograms (reused in phase 3)
    __shared__ unsigned smx[16], smnk[16];
    int bid = blockIdx.x;
    int tid = threadIdx.x;
    int lane = tid & 31;
    int w = tid >> 5;

    // hoisted: zero phase-2 histograms up front, overlapping phase-1 global-load latency
    for (int i = tid; i < HWORDS; i += blockDim.x) sh[i] = 0u;

    // ---------- phase 1: min/max + L1 ----------
    if (bid < 384) {
        // bid 0..191: u columns; 192..383: s columns. Coalesced 8-row warp tiles.
        const float* a = (bid < 192) ? u : s;
        int base = (bid < 192) ? 0 : 16;
        int pb = (bid < 192) ? bid : bid - 192;
        const int stride = 192 * 256;
        const float4* A4 = (const float4*)a;
        int rsub = lane >> 2;      // row-within-8-group
        float4 mn4 = make_float4(__int_as_float(0x7F800000), __int_as_float(0x7F800000),
                                 __int_as_float(0x7F800000), __int_as_float(0x7F800000));
        float4 mx4 = make_float4(__int_as_float(0xFF800000), __int_as_float(0xFF800000),
                                 __int_as_float(0xFF800000), __int_as_float(0xFF800000));
        for (int R = pb * 256 + w * 32; R < n; R += stride) {
#pragma unroll
            for (int sub = 0; sub < 4; sub++) {
                int row = R + sub * 8 + rsub;
                if (row < n) {
                    float4 f = A4[R * 4 + sub * 32 + lane];   // lane-contiguous: row=R+sub*8+lane/4, cols 4*(lane&3)..+3
                    mn4.x = fminf(mn4.x, f.x); mx4.x = fmaxf(mx4.x, f.x);
                    mn4.y = fminf(mn4.y, f.y); mx4.y = fmaxf(mx4.y, f.y);
                    mn4.z = fminf(mn4.z, f.z); mx4.z = fmaxf(mx4.z, f.z);
                    mn4.w = fminf(mn4.w, f.w); mx4.w = fmaxf(mx4.w, f.w);
                }
            }
        }
        // reduce across lanes sharing the same column group (xor of multiples of 4 preserves lane&3)
#pragma unroll
        for (int off = 4; off <= 16; off <<= 1) {
            mn4.x = fminf(mn4.x, __shfl_xor_sync(0xFFFFFFFFu, mn4.x, off));
            mn4.y = fminf(mn4.y, __shfl_xor_sync(0xFFFFFFFFu, mn4.y, off));
            mn4.z = fminf(mn4.z, __shfl_xor_sync(0xFFFFFFFFu, mn4.z, off));
            mn4.w = fminf(mn4.w, __shfl_xor_sync(0xFFFFFFFFu, mn4.w, off));
            mx4.x = fmaxf(mx4.x, __shfl_xor_sync(0xFFFFFFFFu, mx4.x, off));
            mx4.y = fmaxf(mx4.y, __shfl_xor_sync(0xFFFFFFFFu, mx4.y, off));
            mx4.z = fmaxf(mx4.z, __shfl_xor_sync(0xFFFFFFFFu, mx4.z, off));
            mx4.w = fmaxf(mx4.w, __shfl_xor_sync(0xFFFFFFFFu, mx4.w, off));
        }
        if (tid < 16) { smx[tid] = 0u; smnk[tid] = 0u; }
        __syncthreads();
        if (lane < 4) {     // lane g holds groups g -> columns 4g..4g+3
            int c0 = lane * 4;
            atomicMax(&smx[c0 + 0], fenc(mx4.x));  atomicMax(&smnk[c0 + 0], ~fenc(mn4.x));
            atomicMax(&smx[c0 + 1], fenc(mx4.y));  atomicMax(&smnk[c0 + 1], ~fenc(mn4.y));
            atomicMax(&smx[c0 + 2], fenc(mx4.z));  atomicMax(&smnk[c0 + 2], ~fenc(mn4.z));
            atomicMax(&smx[c0 + 3], fenc(mx4.w));  atomicMax(&smnk[c0 + 3], ~fenc(mn4.w));
        }
        __syncthreads();
        if (tid < 16) {
            atomicMax(&g_maxkey[base + tid], smx[tid]);
            atomicMax(&g_minkey[base + tid], smnk[tid]);
        }
    } else {
        // bid 384..443: y_pred minmax + L1 (60 blocks), float4 vectorized
        int pb = bid - 384;
        const int stride4 = 60 * 256;
        int n4 = n >> 2;
        float mn = __int_as_float(0x7F800000), mx = __int_as_float(0xFF800000);
        double acc = 0.0;
        const float4* yp4 = (const float4*)yp;
        const float4* yt4 = (const float4*)yt;
        for (int i = pb * 256 + tid; i < n4; i += stride4) {
            float4 p = yp4[i];
            float4 t = yt4[i];
            mn = fminf(mn, fminf(fminf(p.x, p.y), fminf(p.z, p.w)));
            mx = fmaxf(mx, fmaxf(fmaxf(p.x, p.y), fmaxf(p.z, p.w)));
            float s4 = fabsf(t.x - p.x) + fabsf(t.y - p.y) + fabsf(t.z - p.z) + fabsf(t.w - p.w);
            acc += (double)s4;
        }
        for (int i = (n4 << 2) + pb * 256 + tid; i < n; i += stride4) {
            float v = yp[i];
            mn = fminf(mn, v); mx = fmaxf(mx, v);
            acc += (double)fabsf(yt[i] - v);
        }
#pragma unroll
        for (int o = 16; o; o >>= 1) {
            mn = fminf(mn, __shfl_down_sync(0xFFFFFFFFu, mn, o));
            mx = fmaxf(mx, __shfl_down_sync(0xFFFFFFFFu, mx, o));
            acc += __shfl_down_sync(0xFFFFFFFFu, acc, o);
        }
        if ((tid & 31) == 0) {
            atomicMax(&g_maxkey[32], fenc(mx));
            atomicMax(&g_minkey[32], ~fenc(mn));
            atomicAdd(&g_l1sum, acc);
        }
    }

    // ---------- barrier 1 ----------
    __threadfence();
    __syncthreads();
    if (tid == 0) {
        atomicAdd(&g_arrive1, 1u);
        while (atomicAdd(&g_arrive1, 0u) < GRID_MAIN) __nanosleep(64);
    }
    __syncthreads();

    // ---------- phase 2: histograms, coalesced 8-row warp tiles ----------
    {
        const float* a = (bid < 222) ? u : s;
        int hbase = (bid < 222) ? 0 : 16;
        int pb = (bid < 222) ? bid : bid - 222;
        const int stride = 222 * 256;
        const float4* A4 = (const float4*)a;
        int g = lane & 3;
        int rsub = lane >> 2;

        float inv4[4], ninv4[4];
        int cbase[4];
#pragma unroll
        for (int k = 0; k < 4; k++) {
            int c = 4 * g + k;
            float lo = fdec(~g_minkey[hbase + c]);
            float hi = fdec(g_maxkey[hbase + c]);
            float iv = 1.0f / __fdiv_rn(__fsub_rn(hi, lo), 30.0f);
            inv4[k] = iv;
            ninv4[k] = -lo * iv;
            cbase[k] = c * (15 * NB);
        }
        float ymn = fdec(~g_minkey[32]);
        float yiv = 1.0f / __fdiv_rn(__fsub_rn(fdec(g_maxkey[32]), ymn), 30.0f);
        float yni = -ymn * yiv;

        for (int R = pb * 256 + w * 32; R < n; R += stride) {
#pragma unroll
            for (int sub = 0; sub < 4; sub++) {
                int row = R + sub * 8 + rsub;
                if (row < n) {
                    float4 f = A4[R * 4 + sub * 32 + lane];
                    float yv = __ldg(yp + row);   // 4 lanes/row -> broadcast, 1 line per sub
                    int iy = min((int)fmaf(yv, yiv, yni), 29);
                    unsigned inc = (iy & 1) ? 0x10000u : 1u;
                    int yh = iy >> 1;
                    int ix0 = min((int)fmaf(f.x, inv4[0], ninv4[0]), 29);
                    int ix1 = min((int)fmaf(f.y, inv4[1], ninv4[1]), 29);
                    int ix2 = min((int)fmaf(f.z, inv4[2], ninv4[2]), 29);
                    int ix3 = min((int)fmaf(f.w, inv4[3], ninv4[3]), 29);
                    atomicAdd(&sh[cbase[0] + ix0 * 15 + yh], inc);
                    atomicAdd(&sh[cbase[1] + ix1 * 15 + yh], inc);
                    atomicAdd(&sh[cbase[2] + ix2 * 15 + yh], inc);
                    atomicAdd(&sh[cbase[3] + ix3 * 15 + yh], inc);
                }
            }
        }
        __syncthreads();
        for (int ww = tid; ww < HWORDS; ww += blockDim.x) {
            unsigned x = sh[ww];
            if (!x) continue;
            int c = ww / (15 * NB), rr = ww % (15 * NB);
            int ix = rr / 15, iy2 = (rr % 15) * 2;
            unsigned lo = x & 0xFFFFu, hi = x >> 16;
            if (lo) atomicAdd(&g_hist[hbase + c][ix * NB + iy2], lo);
            if (hi) atomicAdd(&g_hist[hbase + c][ix * NB + iy2 + 1], hi);
        }
    }

    // ---------- barrier 2 (blocks >= FIN_BLOCKS arrive and exit) ----------
    __threadfence();
    __syncthreads();
    if (tid == 0) atomicAdd(&g_arrive2, 1u);
    if (bid >= FIN_BLOCKS) return;
    if (tid == 0) {
        while (atomicAdd(&g_arrive2, 0u) < GRID_MAIN) __nanosleep(64);
    }
    __syncthreads();

    // ---------- phase 3: finalize (blocks 0..79) ----------
    if (bid < 64) {
        int h = bid >> 1;
        int half = bid & 1;
        unsigned* H = g_hist[h];
        float* rs = (float*)sh;
        float* cs = (float*)sh + 32;
        if (tid < NB) {
            unsigned ssum = 0;
#pragma unroll
            for (int j = 0; j < NB; j++) ssum += H[tid * NB + j];
            rs[tid] = (float)ssum;
        } else if (tid >= 32 && tid < 32 + NB) {
            int c = tid - 32;
            unsigned ssum = 0;
#pragma unroll
            for (int i = 0; i < NB; i++) ssum += H[i * NB + c];
            cs[c] = (float)ssum;
        }
        __syncthreads();
        double acc = 0.0;
        int begin = half * 450;
        for (int idx = begin + tid; idx < begin + 450; idx += blockDim.x) {
            int i = idx / NB, j = idx % NB;
            float cnt = (float)H[idx];
            float pxy = (cnt > 0.f) ? __fdiv_rn(cnt, n_total) : 1e-10f;
            float px  = (rs[i] > 0.f) ? __fdiv_rn(rs[i], n_total) : 1e-10f;
            float py  = (cs[j] > 0.f) ? __fdiv_rn(cs[j], n_total) : 1e-10f;
            acc += (double)(pxy * logf(pxy / (px * py)));
        }
#pragma unroll
        for (int o = 16; o; o >>= 1) acc += __shfl_down_sync(0xFFFFFFFFu, acc, o);
        double* wacc = (double*)(sh + 64);
        __shared__ int zeroer;
        if ((tid & 31) == 0) wacc[tid >> 5] = acc;
        __syncthreads();
        if (tid == 0) {
            double sum = 0.0;
            for (int ww = 0; ww < 8; ww++) sum += wacc[ww];
            atomicAdd(&g_mi_hist, sum);
            zeroer = (atomicAdd(&g_hdone[h], 1u) == 1u);  // second finisher resets this hist
        }
        __syncthreads();
        if (zeroer) {
            for (int ww = tid; ww < NB * NB; ww += blockDim.x) H[ww] = 0u;
            if (tid == 0) g_hdone[h] = 0u;
        }
    } else {
        int i = bid - 64;
        int* slu = (int*)sh;
        int* sls = (int*)sh + 16;
        if (tid == 0) {
            float uv[16];
#pragma unroll
            for (int d = 0; d < 16; d++) uv[d] = u[i * 16 + d];
            labelize16(uv, slu);
        } else if (tid == 32) {
            float sv[16];
#pragma unroll
            for (int d = 0; d < 16; d++) sv[d] = s[i * 16 + d];
            labelize16(sv, sls);
        }
        __syncthreads();
        float term = 0.f;
        if (tid < 16) {
            int lj = slu[tid], sj = sls[tid];
            int a2 = 0, b2 = 0, c2 = 0;
#pragma unroll
            for (int k = 0; k < 16; k++) {
                int eu = (slu[k] == lj);
                int es = (sls[k] == sj);
                a2 += eu; b2 += es; c2 += eu & es;
            }
            term = logf((float)(c2 * 16) / (float)(a2 * b2));
        }
        if (tid < 32) {
            double acc = (double)term;
#pragma unroll
            for (int o = 16; o; o >>= 1) acc += __shfl_down_sync(0xFFFFFFFFu, acc, o);
            if (tid == 0) atomicAdd(&g_mi_us, acc * (1.0 / 16.0));
        }
    }

    // ---------- combine + full state reset (last fin block) ----------
    __threadfence();
    __syncthreads();
    if (tid == 0) {
        unsigned ticket = atomicAdd(&g_done, 1u);
        if (ticket == FIN_BLOCKS - 1u) {
            out[0] = (float)(g_l1sum / (double)n_total + 0.1 * g_mi_hist - 0.05 * g_mi_us);
            for (int i = 0; i < 33; i++) { g_maxkey[i] = 0u; g_minkey[i] = 0u; }
            g_l1sum = 0.0; g_mi_hist = 0.0; g_mi_us = 0.0;
            g_arrive1 = 0u; g_arrive2 = 0u;
            __threadfence();
            g_done = 0u;
        }
    }
}

// ---------------- launch ----------------
extern "C" void kernel_launch(void* const* d_in, const int* in_sizes, int n_in,
                              void* d_out, int out_size) {
    const float* y_true = (const float*)d_in[0];
    const float* y_pred = (const float*)d_in[1];
    const float* u_vec  = (const float*)d_in[4];
    const float* s_vec  = (const float*)d_in[5];
    int n = in_sizes[0];

    k_main<<<GRID_MAIN, 256>>>(u_vec, s_vec, y_true, y_pred, n, (float)n, (float*)d_out);
}